// round 7
// baseline (speedup 1.0000x reference)
#include <cuda_runtime.h>
#include <math.h>
#include <stdint.h>

#define EMBED 1024
#define HEADS 16
#define HDIM  64
#define BATCH 4
#define SEQ   2048
#define MTOT  (BATCH * SEQ)   /* 8192 */

#define BK      16            /* GEMM K elements per chunk */
#define NCHUNK  (EMBED / BK)  /* 64 */
#define SSTR    20            /* GEMM smem row stride */

// ---- scratch (device globals; no allocations allowed) ----
__device__ float g_Q[BATCH * HEADS * SEQ * HDIM];  // [B][H][N][Dh]
__device__ float g_K[BATCH * HEADS * SEQ * HDIM];
__device__ float g_V[BATCH * HEADS * SEQ * HDIM];
__device__ float g_C[MTOT * EMBED];                // attention ctx, [B][N][D]

// fp32 -> tf32 round-to-nearest (avoids biased truncation)
__device__ __forceinline__ float ftf32(float x) {
    uint32_t u;
    asm("cvt.rna.tf32.f32 %0, %1;" : "=r"(u) : "f"(x));
    return __uint_as_float(u);
}

// D += A(16x8) * B(8x8), tf32 inputs, fp32 accum
__device__ __forceinline__ void mma_tf32(float* d, const uint32_t* a, const uint32_t* b) {
    asm volatile(
        "mma.sync.aligned.m16n8k8.row.col.f32.tf32.tf32.f32 "
        "{%0,%1,%2,%3}, {%4,%5,%6,%7}, {%8,%9}, {%0,%1,%2,%3};"
        : "+f"(d[0]), "+f"(d[1]), "+f"(d[2]), "+f"(d[3])
        : "r"(a[0]), "r"(a[1]), "r"(a[2]), "r"(a[3]),
          "r"(b[0]), "r"(b[1]));
}

// ============================================================================
// Double-buffered tf32 NT GEMM mainloop (unchanged from round 6, proven)
// ============================================================================
__device__ __forceinline__ void gemm_main(const float* __restrict__ Asrc,
                                          const float* __restrict__ Bw,
                                          int bm, int bn,
                                          float (&acc)[4][4][4])
{
    __shared__ float sA[2][128 * SSTR];
    __shared__ float sB[2][128 * SSTR];

    const int tid  = threadIdx.x;
    const int wid  = tid >> 5;
    const int lane = tid & 31;
    const int lr4  = lane >> 2;
    const int lc4  = lane & 3;
    const int warp_m = (wid & 1) * 64;
    const int warp_n = (wid >> 1) * 32;

    const int grow0 = tid >> 2;
    const int grow1 = grow0 + 64;
    const int gc4   = (tid & 3) << 2;

    float4 pA0, pA1, pB0, pB1;

#define LOADPF(cc) do { int ko = (cc) * BK + gc4; \
    pA0 = *(const float4*)(Asrc + (bm + grow0) * EMBED + ko); \
    pA1 = *(const float4*)(Asrc + (bm + grow1) * EMBED + ko); \
    pB0 = *(const float4*)(Bw   + (bn + grow0) * EMBED + ko); \
    pB1 = *(const float4*)(Bw   + (bn + grow1) * EMBED + ko); } while (0)

#define STOREPF(buf) do { float4 t; \
    t.x = ftf32(pA0.x); t.y = ftf32(pA0.y); t.z = ftf32(pA0.z); t.w = ftf32(pA0.w); \
    *(float4*)&sA[buf][grow0 * SSTR + gc4] = t; \
    t.x = ftf32(pA1.x); t.y = ftf32(pA1.y); t.z = ftf32(pA1.z); t.w = ftf32(pA1.w); \
    *(float4*)&sA[buf][grow1 * SSTR + gc4] = t; \
    t.x = ftf32(pB0.x); t.y = ftf32(pB0.y); t.z = ftf32(pB0.z); t.w = ftf32(pB0.w); \
    *(float4*)&sB[buf][grow0 * SSTR + gc4] = t; \
    t.x = ftf32(pB1.x); t.y = ftf32(pB1.y); t.z = ftf32(pB1.z); t.w = ftf32(pB1.w); \
    *(float4*)&sB[buf][grow1 * SSTR + gc4] = t; } while (0)

    LOADPF(0);
    STOREPF(0);
    LOADPF(1);

    for (int c = 0; c < NCHUNK; c++) {
        __syncthreads();
        if (c + 1 < NCHUNK) {
            STOREPF((c + 1) & 1);
            if (c + 2 < NCHUNK) LOADPF(c + 2);
        }
        const float* cA = sA[c & 1];
        const float* cB = sB[c & 1];

#pragma unroll
        for (int ks = 0; ks < 2; ks++) {
            uint32_t af[4][4], bf[4][2];
            const int kb = ks * 8;
#pragma unroll
            for (int i = 0; i < 4; i++) {
                int m = warp_m + i * 16;
                af[i][0] = *(const uint32_t*)&cA[(m + lr4    ) * SSTR + kb + lc4    ];
                af[i][1] = *(const uint32_t*)&cA[(m + lr4 + 8) * SSTR + kb + lc4    ];
                af[i][2] = *(const uint32_t*)&cA[(m + lr4    ) * SSTR + kb + lc4 + 4];
                af[i][3] = *(const uint32_t*)&cA[(m + lr4 + 8) * SSTR + kb + lc4 + 4];
            }
#pragma unroll
            for (int j = 0; j < 4; j++) {
                int n = warp_n + j * 8;
                bf[j][0] = *(const uint32_t*)&cB[(n + lr4) * SSTR + kb + lc4    ];
                bf[j][1] = *(const uint32_t*)&cB[(n + lr4) * SSTR + kb + lc4 + 4];
            }
#pragma unroll
            for (int i = 0; i < 4; i++)
#pragma unroll
                for (int j = 0; j < 4; j++)
                    mma_tf32(acc[i][j], af[i], bf[j]);
        }
    }
#undef LOADPF
#undef STOREPF
}

// ============================================================================
// Fused QKV projection (unchanged from round 6)
// ============================================================================
__global__ void __launch_bounds__(256, 2)
qkv_gemm(const float* __restrict__ x,
         const float* __restrict__ Wq, const float* __restrict__ Wk,
         const float* __restrict__ Wv,
         const float* __restrict__ bq, const float* __restrict__ bk,
         const float* __restrict__ bv)
{
    const int z = blockIdx.z;
    const float* Bw   = (z == 0) ? Wq : (z == 1) ? Wk : Wv;
    const float* bias = (z == 0) ? bq : (z == 1) ? bk : bv;
    float* C          = (z == 0) ? g_Q : (z == 1) ? g_K : g_V;

    const int bm = blockIdx.x * 128;
    const int bn = blockIdx.y * 128;

    float acc[4][4][4];
#pragma unroll
    for (int i = 0; i < 4; i++)
#pragma unroll
        for (int j = 0; j < 4; j++)
#pragma unroll
            for (int r = 0; r < 4; r++) acc[i][j][r] = 0.f;

    gemm_main(x, Bw, bm, bn, acc);

    const int tid  = threadIdx.x;
    const int wid  = tid >> 5;
    const int lane = tid & 31;
    const int lr4  = lane >> 2;
    const int lc4  = lane & 3;
    const int warp_m = (wid & 1) * 64;
    const int warp_n = (wid >> 1) * 32;

#pragma unroll
    for (int i = 0; i < 4; i++) {
#pragma unroll
        for (int j = 0; j < 4; j++) {
            int row0 = bm + warp_m + i * 16 + lr4;
            int col0 = bn + warp_n + j * 8 + 2 * lc4;
#pragma unroll
            for (int half = 0; half < 2; half++) {
                int row = row0 + half * 8;
                float2 o;
                o.x = acc[i][j][half * 2 + 0] + __ldg(bias + col0 + 0);
                o.y = acc[i][j][half * 2 + 1] + __ldg(bias + col0 + 1);
                int b   = row >> 11;
                int tok = row & 2047;
                int h   = col0 >> 6;
                int dh  = col0 & 63;
                *(float2*)&C[(((b << 4) + h) * SEQ + tok) * HDIM + dh] = o;
            }
        }
    }
}

// ============================================================================
// Output projection (unchanged from round 6)
// ============================================================================
__global__ void __launch_bounds__(256, 2)
out_gemm(const float* __restrict__ Wo, float* __restrict__ out)
{
    const int bm = blockIdx.x * 128;
    const int bn = blockIdx.y * 128;

    float acc[4][4][4];
#pragma unroll
    for (int i = 0; i < 4; i++)
#pragma unroll
        for (int j = 0; j < 4; j++)
#pragma unroll
            for (int r = 0; r < 4; r++) acc[i][j][r] = 0.f;

    gemm_main((const float*)g_C, Wo, bm, bn, acc);

    const int tid  = threadIdx.x;
    const int wid  = tid >> 5;
    const int lane = tid & 31;
    const int lr4  = lane >> 2;
    const int lc4  = lane & 3;
    const int warp_m = (wid & 1) * 64;
    const int warp_n = (wid >> 1) * 32;

#pragma unroll
    for (int i = 0; i < 4; i++) {
#pragma unroll
        for (int j = 0; j < 4; j++) {
            int row0 = bm + warp_m + i * 16 + lr4;
            int col0 = bn + warp_n + j * 8 + 2 * lc4;
#pragma unroll
            for (int half = 0; half < 2; half++) {
                int row = row0 + half * 8;
                float2 o;
                o.x = acc[i][j][half * 2 + 0];
                o.y = acc[i][j][half * 2 + 1];
                *(float2*)&out[row * EMBED + col0] = o;
            }
        }
    }
}

// ============================================================================
// Flash attention v2: warp tile 32q x 64kv, Q register-resident.
// BQ=256, 8 warps, one (b,h) per block. smem: single K + Vt buffer (32KB).
// Each B-fragment LDS feeds 2 mmas (mf=0,1) -> smem read bytes per mma halved
// vs round-5 kernel; all Q smem traffic eliminated.
// Rounding points (ftf32 on Q,K,V,P) identical to round 5.
// ============================================================================
__global__ void __launch_bounds__(256)
attn_mma()
{
    __shared__ float sK [64 * 64];
    __shared__ float sVt[64 * 64];

    const int tid  = threadIdx.x;
    const int wid  = tid >> 5;
    const int lane = tid & 31;
    const int lr4  = lane >> 2;
    const int lc4  = lane & 3;
    const int wq   = wid * 32;            // warp's q base within block
    const int q0   = blockIdx.x * 256;
    const int h    = blockIdx.y;
    const int b    = blockIdx.z;

    const float* Qb = g_Q + ((b * HEADS + h) * SEQ + q0 + wq) * HDIM;
    const float* Kb = g_K + ((b * HEADS + h) * SEQ) * HDIM;
    const float* Vb = g_V + ((b * HEADS + h) * SEQ) * HDIM;

    const uint32_t* sKu  = (const uint32_t*)sK;
    const uint32_t* sVtu = (const uint32_t*)sVt;

    // ---- Q fragments -> registers (pre-scaled by 0.125, tf32-rounded) ----
    uint32_t qf[2][8][4];
#pragma unroll
    for (int mf = 0; mf < 2; mf++) {
        const int r0 = mf * 16 + lr4;
#pragma unroll
        for (int k = 0; k < 8; k++) {
            const int c0 = k * 8 + lc4;
            qf[mf][k][0] = __float_as_uint(ftf32(Qb[ r0      * HDIM + c0    ] * 0.125f));
            qf[mf][k][1] = __float_as_uint(ftf32(Qb[(r0 + 8) * HDIM + c0    ] * 0.125f));
            qf[mf][k][2] = __float_as_uint(ftf32(Qb[ r0      * HDIM + c0 + 4] * 0.125f));
            qf[mf][k][3] = __float_as_uint(ftf32(Qb[(r0 + 8) * HDIM + c0 + 4] * 0.125f));
        }
    }

    float out[2][8][4];
#pragma unroll
    for (int mf = 0; mf < 2; mf++)
#pragma unroll
        for (int n = 0; n < 8; n++)
#pragma unroll
            for (int c = 0; c < 4; c++) out[mf][n][c] = 0.f;
    float mM[2][2], lL[2][2];
#pragma unroll
    for (int mf = 0; mf < 2; mf++) {
        mM[mf][0] = -INFINITY; mM[mf][1] = -INFINITY;
        lL[mf][0] = 0.f;       lL[mf][1] = 0.f;
    }

    for (int kv0 = 0; kv0 < SEQ; kv0 += 64) {
        __syncthreads();   // previous tile's K/Vt reads complete

        // ---- load phase: K (swizzled) + Vt (transposed, kv-permuted) ----
#pragma unroll
        for (int r = 0; r < 4; r++) {
            int idx = tid + r * 256;
            int row = idx >> 4;
            int c4  = (idx & 15) << 2;
            float4 kv = *(const float4*)&Kb[(kv0 + row) * HDIM + c4];
            float4 t;
            t.x = ftf32(kv.x); t.y = ftf32(kv.y); t.z = ftf32(kv.z); t.w = ftf32(kv.w);
            *(float4*)&sK[row * 64 + (c4 ^ ((row & 7) << 2))] = t;
        }
#pragma unroll
        for (int r = 0; r < 4; r++) {
            int kvr = (tid >> 2) & 63;
            int c4  = ((tid & 3) << 2) + (r << 4);
            float4 vv = *(const float4*)&Vb[(kv0 + kvr) * HDIM + c4];
            int colv = (kvr & 56) + ((kvr >> 1) & 3) + ((kvr & 1) << 2);
            sVt[(c4 + 0) * 64 + (colv ^ (((c4 + 0) & 7) << 2))] = ftf32(vv.x);
            sVt[(c4 + 1) * 64 + (colv ^ (((c4 + 1) & 7) << 2))] = ftf32(vv.y);
            sVt[(c4 + 2) * 64 + (colv ^ (((c4 + 2) & 7) << 2))] = ftf32(vv.z);
            sVt[(c4 + 3) * 64 + (colv ^ (((c4 + 3) & 7) << 2))] = ftf32(vv.w);
        }
        __syncthreads();

        // ---- QK^T: s[mf][j] over 8 kv-groups; B-frag shared across mf ----
        float s[2][8][4];
#pragma unroll
        for (int mf = 0; mf < 2; mf++)
#pragma unroll
            for (int j = 0; j < 8; j++)
#pragma unroll
                for (int c = 0; c < 4; c++) s[mf][j][c] = 0.f;

#pragma unroll
        for (int k = 0; k < 8; k++) {
            const int kb = k * 8;
#pragma unroll
            for (int j = 0; j < 8; j++) {
                uint32_t bf[2];
                const int rb = j * 8 + lr4;
                bf[0] = sKu[rb * 64 + ((kb + lc4    ) ^ (lr4 << 2))];
                bf[1] = sKu[rb * 64 + ((kb + lc4 + 4) ^ (lr4 << 2))];
                mma_tf32(s[0][j], qf[0][k], bf);
                mma_tf32(s[1][j], qf[1][k], bf);
            }
        }

        // ---- online softmax per m-fragment (registers + 2 shfls) ----
#pragma unroll
        for (int mf = 0; mf < 2; mf++) {
            float mx0 = -INFINITY, mx1 = -INFINITY;
#pragma unroll
            for (int j = 0; j < 8; j++) {
                mx0 = fmaxf(mx0, fmaxf(s[mf][j][0], s[mf][j][1]));
                mx1 = fmaxf(mx1, fmaxf(s[mf][j][2], s[mf][j][3]));
            }
            mx0 = fmaxf(mx0, __shfl_xor_sync(0xffffffffu, mx0, 1));
            mx0 = fmaxf(mx0, __shfl_xor_sync(0xffffffffu, mx0, 2));
            mx1 = fmaxf(mx1, __shfl_xor_sync(0xffffffffu, mx1, 1));
            mx1 = fmaxf(mx1, __shfl_xor_sync(0xffffffffu, mx1, 2));
            float mn0 = fmaxf(mM[mf][0], mx0), mn1 = fmaxf(mM[mf][1], mx1);
            float rs0 = __expf(mM[mf][0] - mn0), rs1 = __expf(mM[mf][1] - mn1);
            mM[mf][0] = mn0; mM[mf][1] = mn1;
            float sum0 = 0.f, sum1 = 0.f;
#pragma unroll
            for (int j = 0; j < 8; j++) {
                s[mf][j][0] = __expf(s[mf][j][0] - mn0);
                s[mf][j][1] = __expf(s[mf][j][1] - mn0);
                sum0 += s[mf][j][0] + s[mf][j][1];
                s[mf][j][2] = __expf(s[mf][j][2] - mn1);
                s[mf][j][3] = __expf(s[mf][j][3] - mn1);
                sum1 += s[mf][j][2] + s[mf][j][3];
            }
            sum0 += __shfl_xor_sync(0xffffffffu, sum0, 1);
            sum0 += __shfl_xor_sync(0xffffffffu, sum0, 2);
            sum1 += __shfl_xor_sync(0xffffffffu, sum1, 1);
            sum1 += __shfl_xor_sync(0xffffffffu, sum1, 2);
            lL[mf][0] = lL[mf][0] * rs0 + sum0;
            lL[mf][1] = lL[mf][1] * rs1 + sum1;
#pragma unroll
            for (int n = 0; n < 8; n++) {
                out[mf][n][0] *= rs0; out[mf][n][1] *= rs0;
                out[mf][n][2] *= rs1; out[mf][n][3] *= rs1;
            }
#pragma unroll
            for (int j = 0; j < 8; j++)
#pragma unroll
                for (int c = 0; c < 4; c++) s[mf][j][c] = ftf32(s[mf][j][c]);
        }

        // ---- PV: A-frag = (c0,c2,c1,c3) of s; B-frag shared across mf ----
#pragma unroll
        for (int j = 0; j < 8; j++) {
            uint32_t a0[4], a1[4];
            a0[0] = __float_as_uint(s[0][j][0]);
            a0[1] = __float_as_uint(s[0][j][2]);
            a0[2] = __float_as_uint(s[0][j][1]);
            a0[3] = __float_as_uint(s[0][j][3]);
            a1[0] = __float_as_uint(s[1][j][0]);
            a1[1] = __float_as_uint(s[1][j][2]);
            a1[2] = __float_as_uint(s[1][j][1]);
            a1[3] = __float_as_uint(s[1][j][3]);
            const int kb = j * 8;
#pragma unroll
            for (int n = 0; n < 8; n++) {
                uint32_t bf[2];
                const int rb = n * 8 + lr4;
                bf[0] = sVtu[rb * 64 + ((kb + lc4    ) ^ (lr4 << 2))];
                bf[1] = sVtu[rb * 64 + ((kb + lc4 + 4) ^ (lr4 << 2))];
                mma_tf32(out[0][n], a0, bf);
                mma_tf32(out[1][n], a1, bf);
            }
        }
    }

    // ---- epilogue ----
    float* Cb = g_C + (b * SEQ + q0 + wq) * EMBED + h * HDIM;
#pragma unroll
    for (int mf = 0; mf < 2; mf++) {
        const float inv0 = 1.f / lL[mf][0], inv1 = 1.f / lL[mf][1];
        const int r0 = mf * 16 + lr4, r1 = r0 + 8;
#pragma unroll
        for (int n = 0; n < 8; n++) {
            int col = n * 8 + 2 * lc4;
            float2 o;
            o.x = out[mf][n][0] * inv0; o.y = out[mf][n][1] * inv0;
            *(float2*)&Cb[r0 * EMBED + col] = o;
            o.x = out[mf][n][2] * inv1; o.y = out[mf][n][3] * inv1;
            *(float2*)&Cb[r1 * EMBED + col] = o;
        }
    }
}

// ============================================================================
extern "C" void kernel_launch(void* const* d_in, const int* in_sizes, int n_in,
                              void* d_out, int out_size)
{
    (void)in_sizes; (void)n_in; (void)out_size;
    const float* x  = (const float*)d_in[0];
    const float* Wq = (const float*)d_in[1];
    const float* bq = (const float*)d_in[2];
    const float* Wk = (const float*)d_in[3];
    const float* bk = (const float*)d_in[4];
    const float* Wv = (const float*)d_in[5];
    const float* bv = (const float*)d_in[6];
    const float* Wo = (const float*)d_in[7];
    float* out = (float*)d_out;

    qkv_gemm<<<dim3(MTOT / 128, EMBED / 128, 3), 256>>>(x, Wq, Wk, Wv, bq, bk, bv);

    attn_mma<<<dim3(SEQ / 256, HEADS, BATCH), 256>>>();

    out_gemm<<<dim3(MTOT / 128, EMBED / 128), 256>>>(Wo, out);
}

// round 8
// speedup vs baseline: 1.5664x; 1.5664x over previous
#include <cuda_runtime.h>
#include <cuda_fp16.h>
#include <math.h>
#include <stdint.h>

#define EMBED 1024
#define HEADS 16
#define HDIM  64
#define BATCH 4
#define SEQ   2048
#define MTOT  (BATCH * SEQ)   /* 8192 */

#define BK      16            /* GEMM K elements per chunk (= one k16 mma) */
#define NCHUNK  (EMBED / BK)  /* 64 */
#define SSTRW   12            /* GEMM smem row stride in 32-bit words */

// ---- scratch (device globals; no allocations allowed) ----
__device__ float g_Q[BATCH * HEADS * SEQ * HDIM];  // [B][H][N][Dh]
__device__ float g_K[BATCH * HEADS * SEQ * HDIM];
__device__ float g_V[BATCH * HEADS * SEQ * HDIM];
__device__ float g_C[MTOT * EMBED];                // attention ctx, [B][N][D]

// pack two floats -> f16x2 (round-to-nearest; .x = lo)
__device__ __forceinline__ uint32_t h2(float lo, float hi) {
    __half2 h = __floats2half2_rn(lo, hi);
    return *(uint32_t*)&h;
}

// D += A(16x16) * B(16x8), f16 inputs, f32 accum
__device__ __forceinline__ void mma_f16(float* d, const uint32_t* a, const uint32_t* b) {
    asm volatile(
        "mma.sync.aligned.m16n8k16.row.col.f32.f16.f16.f32 "
        "{%0,%1,%2,%3}, {%4,%5,%6,%7}, {%8,%9}, {%0,%1,%2,%3};"
        : "+f"(d[0]), "+f"(d[1]), "+f"(d[2]), "+f"(d[3])
        : "r"(a[0]), "r"(a[1]), "r"(a[2]), "r"(a[3]),
          "r"(b[0]), "r"(b[1]));
}

// ============================================================================
// Double-buffered fp16 NT GEMM mainloop.
// BM=BN=128, BK=16, 256 threads (8 warps, 2m x 4n), warp tile 64x32.
// smem as packed halves (uint32 words), row stride 12 words (conflict-free).
// ============================================================================
__device__ __forceinline__ void gemm_main(const float* __restrict__ Asrc,
                                          const float* __restrict__ Bw,
                                          int bm, int bn,
                                          float (&acc)[4][4][4])
{
    __shared__ uint32_t sA[2][128 * SSTRW];
    __shared__ uint32_t sB[2][128 * SSTRW];

    const int tid  = threadIdx.x;
    const int wid  = tid >> 5;
    const int lane = tid & 31;
    const int lr4  = lane >> 2;
    const int lc4  = lane & 3;
    const int warp_m = (wid & 1) * 64;
    const int warp_n = (wid >> 1) * 32;

    const int grow0 = tid >> 2;          // 0..63
    const int grow1 = grow0 + 64;        // 64..127
    const int gc4   = (tid & 3) << 2;    // float col 0,4,8,12
    const int gw    = gc4 >> 1;          // word col 0,2,4,6

    float4 pA0, pA1, pB0, pB1;

#define LOADPF(cc) do { int ko = (cc) * BK + gc4; \
    pA0 = *(const float4*)(Asrc + (bm + grow0) * EMBED + ko); \
    pA1 = *(const float4*)(Asrc + (bm + grow1) * EMBED + ko); \
    pB0 = *(const float4*)(Bw   + (bn + grow0) * EMBED + ko); \
    pB1 = *(const float4*)(Bw   + (bn + grow1) * EMBED + ko); } while (0)

#define STOREPF(buf) do { uint2 w; \
    w.x = h2(pA0.x, pA0.y); w.y = h2(pA0.z, pA0.w); \
    *(uint2*)&sA[buf][grow0 * SSTRW + gw] = w; \
    w.x = h2(pA1.x, pA1.y); w.y = h2(pA1.z, pA1.w); \
    *(uint2*)&sA[buf][grow1 * SSTRW + gw] = w; \
    w.x = h2(pB0.x, pB0.y); w.y = h2(pB0.z, pB0.w); \
    *(uint2*)&sB[buf][grow0 * SSTRW + gw] = w; \
    w.x = h2(pB1.x, pB1.y); w.y = h2(pB1.z, pB1.w); \
    *(uint2*)&sB[buf][grow1 * SSTRW + gw] = w; } while (0)

    LOADPF(0);
    STOREPF(0);
    LOADPF(1);

    for (int c = 0; c < NCHUNK; c++) {
        __syncthreads();
        if (c + 1 < NCHUNK) {
            STOREPF((c + 1) & 1);
            if (c + 2 < NCHUNK) LOADPF(c + 2);
        }
        const uint32_t* cA = sA[c & 1];
        const uint32_t* cB = sB[c & 1];

        uint32_t af[4][4], bf[4][2];
#pragma unroll
        for (int i = 0; i < 4; i++) {
            int m = warp_m + i * 16;
            af[i][0] = cA[(m + lr4    ) * SSTRW + lc4    ];
            af[i][1] = cA[(m + lr4 + 8) * SSTRW + lc4    ];
            af[i][2] = cA[(m + lr4    ) * SSTRW + lc4 + 4];
            af[i][3] = cA[(m + lr4 + 8) * SSTRW + lc4 + 4];
        }
#pragma unroll
        for (int j = 0; j < 4; j++) {
            int n = warp_n + j * 8;
            bf[j][0] = cB[(n + lr4) * SSTRW + lc4    ];
            bf[j][1] = cB[(n + lr4) * SSTRW + lc4 + 4];
        }
#pragma unroll
        for (int i = 0; i < 4; i++)
#pragma unroll
            for (int j = 0; j < 4; j++)
                mma_f16(acc[i][j], af[i], bf[j]);
    }
#undef LOADPF
#undef STOREPF
}

// ============================================================================
// Fused QKV projection (epilogue unchanged; accumulators are f32)
// ============================================================================
__global__ void __launch_bounds__(256, 2)
qkv_gemm(const float* __restrict__ x,
         const float* __restrict__ Wq, const float* __restrict__ Wk,
         const float* __restrict__ Wv,
         const float* __restrict__ bq, const float* __restrict__ bk,
         const float* __restrict__ bv)
{
    const int z = blockIdx.z;
    const float* Bw   = (z == 0) ? Wq : (z == 1) ? Wk : Wv;
    const float* bias = (z == 0) ? bq : (z == 1) ? bk : bv;
    float* C          = (z == 0) ? g_Q : (z == 1) ? g_K : g_V;

    const int bm = blockIdx.x * 128;
    const int bn = blockIdx.y * 128;

    float acc[4][4][4];
#pragma unroll
    for (int i = 0; i < 4; i++)
#pragma unroll
        for (int j = 0; j < 4; j++)
#pragma unroll
            for (int r = 0; r < 4; r++) acc[i][j][r] = 0.f;

    gemm_main(x, Bw, bm, bn, acc);

    const int tid  = threadIdx.x;
    const int wid  = tid >> 5;
    const int lane = tid & 31;
    const int lr4  = lane >> 2;
    const int lc4  = lane & 3;
    const int warp_m = (wid & 1) * 64;
    const int warp_n = (wid >> 1) * 32;

#pragma unroll
    for (int i = 0; i < 4; i++) {
#pragma unroll
        for (int j = 0; j < 4; j++) {
            int row0 = bm + warp_m + i * 16 + lr4;
            int col0 = bn + warp_n + j * 8 + 2 * lc4;
#pragma unroll
            for (int half = 0; half < 2; half++) {
                int row = row0 + half * 8;
                float2 o;
                o.x = acc[i][j][half * 2 + 0] + __ldg(bias + col0 + 0);
                o.y = acc[i][j][half * 2 + 1] + __ldg(bias + col0 + 1);
                int b   = row >> 11;
                int tok = row & 2047;
                int h   = col0 >> 6;
                int dh  = col0 & 63;
                *(float2*)&C[(((b << 4) + h) * SEQ + tok) * HDIM + dh] = o;
            }
        }
    }
}

// ============================================================================
// Output projection
// ============================================================================
__global__ void __launch_bounds__(256, 2)
out_gemm(const float* __restrict__ Wo, float* __restrict__ out)
{
    const int bm = blockIdx.x * 128;
    const int bn = blockIdx.y * 128;

    float acc[4][4][4];
#pragma unroll
    for (int i = 0; i < 4; i++)
#pragma unroll
        for (int j = 0; j < 4; j++)
#pragma unroll
            for (int r = 0; r < 4; r++) acc[i][j][r] = 0.f;

    gemm_main((const float*)g_C, Wo, bm, bn, acc);

    const int tid  = threadIdx.x;
    const int wid  = tid >> 5;
    const int lane = tid & 31;
    const int lr4  = lane >> 2;
    const int lc4  = lane & 3;
    const int warp_m = (wid & 1) * 64;
    const int warp_n = (wid >> 1) * 32;

#pragma unroll
    for (int i = 0; i < 4; i++) {
#pragma unroll
        for (int j = 0; j < 4; j++) {
            int row0 = bm + warp_m + i * 16 + lr4;
            int col0 = bn + warp_n + j * 8 + 2 * lc4;
#pragma unroll
            for (int half = 0; half < 2; half++) {
                int row = row0 + half * 8;
                float2 o;
                o.x = acc[i][j][half * 2 + 0];
                o.y = acc[i][j][half * 2 + 1];
                *(float2*)&out[row * EMBED + col0] = o;
            }
        }
    }
}

// ============================================================================
// Flash attention, fp16 mma. BQ=128, 8 warps x 16 q-rows (round-5 shape).
// Q register-resident (16 regs/thread). smem: sK + sVt, 8KB each, half-packed.
// QK: 4 k16 steps; PV: scores pack straight into A-fragments (no smem P).
// 2 syncs per kv tile. XOR swizzle (word col ^ (row&7)<<2) on 32-word rows.
// ============================================================================
__global__ void __launch_bounds__(256, 2)
attn_mma()
{
    __shared__ uint32_t sK [64 * 32];
    __shared__ uint32_t sVt[64 * 32];

    const int tid  = threadIdx.x;
    const int wid  = tid >> 5;
    const int lane = tid & 31;
    const int lr4  = lane >> 2;
    const int lc4  = lane & 3;
    const int warp_m = wid * 16;
    const int q0 = blockIdx.x * 128;
    const int h  = blockIdx.y;
    const int b  = blockIdx.z;

    const float* Qb = g_Q + ((b * HEADS + h) * SEQ + q0) * HDIM;
    const float* Kb = g_K + ((b * HEADS + h) * SEQ) * HDIM;
    const float* Vb = g_V + ((b * HEADS + h) * SEQ) * HDIM;

    // ---- Q fragments -> registers (scaled by Dh^-0.5 = 0.125) ----
    uint32_t qf[4][4];
    {
        const float* qr0 = Qb + (warp_m + lr4) * HDIM;
        const float* qr1 = qr0 + 8 * HDIM;
#pragma unroll
        for (int ks = 0; ks < 4; ks++) {
            int c = ks * 16 + 2 * lc4;
            qf[ks][0] = h2(qr0[c    ] * 0.125f, qr0[c + 1] * 0.125f);
            qf[ks][1] = h2(qr1[c    ] * 0.125f, qr1[c + 1] * 0.125f);
            qf[ks][2] = h2(qr0[c + 8] * 0.125f, qr0[c + 9] * 0.125f);
            qf[ks][3] = h2(qr1[c + 8] * 0.125f, qr1[c + 9] * 0.125f);
        }
    }

    float out[8][4];
#pragma unroll
    for (int n = 0; n < 8; n++)
#pragma unroll
        for (int c = 0; c < 4; c++) out[n][c] = 0.f;
    float m0 = -INFINITY, m1 = -INFINITY, l0 = 0.f, l1 = 0.f;

    for (int kv0 = 0; kv0 < SEQ; kv0 += 64) {
        __syncthreads();   // previous tile's sK/sVt reads complete

        // ---- K tile -> sK halves (rows=kv, 32 words of d), swizzled ----
#pragma unroll
        for (int r = 0; r < 4; r++) {
            int idx = tid + r * 256;
            int row = idx >> 4;
            int wc  = (idx & 15) << 1;     // word col 0..30 even
            float4 kv = *(const float4*)&Kb[(kv0 + row) * HDIM + (wc << 1)];
            uint2 w;
            w.x = h2(kv.x, kv.y);
            w.y = h2(kv.z, kv.w);
            *(uint2*)&sK[row * 32 + (wc ^ ((row & 7) << 2))] = w;
        }
        // ---- V tile -> sVt transposed halves (rows=d, words = kv pairs) ----
#pragma unroll
        for (int r = 0; r < 2; r++) {
            int t2  = tid + r * 256;
            int kv2 = t2 >> 4;             // 0..31 (kv pair)
            int d4  = (t2 & 15) << 2;      // 0..60
            float4 v0 = *(const float4*)&Vb[(kv0 + 2 * kv2    ) * HDIM + d4];
            float4 v1 = *(const float4*)&Vb[(kv0 + 2 * kv2 + 1) * HDIM + d4];
            sVt[(d4 + 0) * 32 + (kv2 ^ (((d4 + 0) & 7) << 2))] = h2(v0.x, v1.x);
            sVt[(d4 + 1) * 32 + (kv2 ^ (((d4 + 1) & 7) << 2))] = h2(v0.y, v1.y);
            sVt[(d4 + 2) * 32 + (kv2 ^ (((d4 + 2) & 7) << 2))] = h2(v0.z, v1.z);
            sVt[(d4 + 3) * 32 + (kv2 ^ (((d4 + 3) & 7) << 2))] = h2(v0.w, v1.w);
        }
        __syncthreads();

        // ---- QK^T: 4 k16 steps x 8 kv-tiles ----
        float s[8][4];
#pragma unroll
        for (int j = 0; j < 8; j++)
#pragma unroll
            for (int c = 0; c < 4; c++) s[j][c] = 0.f;

#pragma unroll
        for (int ks = 0; ks < 4; ks++) {
            const int kb = ks * 8;
#pragma unroll
            for (int j = 0; j < 8; j++) {
                uint32_t bf[2];
                const int rb = j * 8 + lr4;
                bf[0] = sK[rb * 32 + ((kb + lc4    ) ^ (lr4 << 2))];
                bf[1] = sK[rb * 32 + ((kb + lc4 + 4) ^ (lr4 << 2))];
                mma_f16(s[j], qf[ks], bf);
            }
        }

        // ---- online softmax (registers + 2 shfls per row-half) ----
        float mx0 = -INFINITY, mx1 = -INFINITY;
#pragma unroll
        for (int j = 0; j < 8; j++) {
            mx0 = fmaxf(mx0, fmaxf(s[j][0], s[j][1]));
            mx1 = fmaxf(mx1, fmaxf(s[j][2], s[j][3]));
        }
        mx0 = fmaxf(mx0, __shfl_xor_sync(0xffffffffu, mx0, 1));
        mx0 = fmaxf(mx0, __shfl_xor_sync(0xffffffffu, mx0, 2));
        mx1 = fmaxf(mx1, __shfl_xor_sync(0xffffffffu, mx1, 1));
        mx1 = fmaxf(mx1, __shfl_xor_sync(0xffffffffu, mx1, 2));
        float mn0 = fmaxf(m0, mx0), mn1 = fmaxf(m1, mx1);
        float rs0 = __expf(m0 - mn0), rs1 = __expf(m1 - mn1);
        m0 = mn0; m1 = mn1;
        float sum0 = 0.f, sum1 = 0.f;
#pragma unroll
        for (int j = 0; j < 8; j++) {
            s[j][0] = __expf(s[j][0] - mn0);
            s[j][1] = __expf(s[j][1] - mn0);
            sum0 += s[j][0] + s[j][1];
            s[j][2] = __expf(s[j][2] - mn1);
            s[j][3] = __expf(s[j][3] - mn1);
            sum1 += s[j][2] + s[j][3];
        }
        sum0 += __shfl_xor_sync(0xffffffffu, sum0, 1);
        sum0 += __shfl_xor_sync(0xffffffffu, sum0, 2);
        sum1 += __shfl_xor_sync(0xffffffffu, sum1, 1);
        sum1 += __shfl_xor_sync(0xffffffffu, sum1, 2);
        l0 = l0 * rs0 + sum0;
        l1 = l1 * rs1 + sum1;
#pragma unroll
        for (int n = 0; n < 8; n++) {
            out[n][0] *= rs0; out[n][1] *= rs0;
            out[n][2] *= rs1; out[n][3] *= rs1;
        }

        // ---- PV: 4 k16 steps (pairs of score tiles) x 8 d-tiles ----
#pragma unroll
        for (int jp = 0; jp < 4; jp++) {
            uint32_t a[4];
            a[0] = h2(s[2 * jp    ][0], s[2 * jp    ][1]);
            a[1] = h2(s[2 * jp    ][2], s[2 * jp    ][3]);
            a[2] = h2(s[2 * jp + 1][0], s[2 * jp + 1][1]);
            a[3] = h2(s[2 * jp + 1][2], s[2 * jp + 1][3]);
            const int kb = jp * 8;
#pragma unroll
            for (int n = 0; n < 8; n++) {
                uint32_t bf[2];
                const int rb = n * 8 + lr4;
                bf[0] = sVt[rb * 32 + ((kb + lc4    ) ^ (lr4 << 2))];
                bf[1] = sVt[rb * 32 + ((kb + lc4 + 4) ^ (lr4 << 2))];
                mma_f16(out[n], a, bf);
            }
        }
    }

    // ---- epilogue: ctx[b][q][h*64 + dh] ----
    const float inv0 = 1.f / l0, inv1 = 1.f / l1;
    float* Cb = g_C + (b * SEQ + q0) * EMBED + h * HDIM;
    const int r0 = warp_m + lr4, r1 = r0 + 8;
#pragma unroll
    for (int n = 0; n < 8; n++) {
        int col = n * 8 + 2 * lc4;
        float2 o;
        o.x = out[n][0] * inv0; o.y = out[n][1] * inv0;
        *(float2*)&Cb[r0 * EMBED + col] = o;
        o.x = out[n][2] * inv1; o.y = out[n][3] * inv1;
        *(float2*)&Cb[r1 * EMBED + col] = o;
    }
}

// ============================================================================
extern "C" void kernel_launch(void* const* d_in, const int* in_sizes, int n_in,
                              void* d_out, int out_size)
{
    (void)in_sizes; (void)n_in; (void)out_size;
    const float* x  = (const float*)d_in[0];
    const float* Wq = (const float*)d_in[1];
    const float* bq = (const float*)d_in[2];
    const float* Wk = (const float*)d_in[3];
    const float* bk = (const float*)d_in[4];
    const float* Wv = (const float*)d_in[5];
    const float* bv = (const float*)d_in[6];
    const float* Wo = (const float*)d_in[7];
    float* out = (float*)d_out;

    qkv_gemm<<<dim3(MTOT / 128, EMBED / 128, 3), 256>>>(x, Wq, Wk, Wv, bq, bk, bv);

    attn_mma<<<dim3(SEQ / 128, HEADS, BATCH), 256>>>();

    out_gemm<<<dim3(MTOT / 128, EMBED / 128), 256>>>(Wo, out);
}

// round 9
// speedup vs baseline: 1.7119x; 1.0929x over previous
#include <cuda_runtime.h>
#include <cuda_fp16.h>
#include <math.h>
#include <stdint.h>

#define EMBED 1024
#define HEADS 16
#define HDIM  64
#define BATCH 4
#define SEQ   2048
#define MTOT  (BATCH * SEQ)   /* 8192 */

#define BKC     32            /* GEMM K floats per chunk (2 x k16 mma) */
#define NCHUNK  (EMBED / BKC) /* 32 */
#define SSTRW   20            /* GEMM smem row stride in 32-bit words (16 data + 4 pad) */

// ---- scratch (device globals; no allocations allowed) ----
__device__ float g_Q[BATCH * HEADS * SEQ * HDIM];  // [B][H][N][Dh]
__device__ float g_K[BATCH * HEADS * SEQ * HDIM];
__device__ float g_V[BATCH * HEADS * SEQ * HDIM];
__device__ float g_C[MTOT * EMBED];                // attention ctx, [B][N][D]

// pack two floats -> f16x2 (round-to-nearest; .x = lo)
__device__ __forceinline__ uint32_t h2(float lo, float hi) {
    __half2 h = __floats2half2_rn(lo, hi);
    return *(uint32_t*)&h;
}

// D += A(16x16) * B(16x8), f16 inputs, f32 accum
__device__ __forceinline__ void mma_f16(float* d, const uint32_t* a, const uint32_t* b) {
    asm volatile(
        "mma.sync.aligned.m16n8k16.row.col.f32.f16.f16.f32 "
        "{%0,%1,%2,%3}, {%4,%5,%6,%7}, {%8,%9}, {%0,%1,%2,%3};"
        : "+f"(d[0]), "+f"(d[1]), "+f"(d[2]), "+f"(d[3])
        : "r"(a[0]), "r"(a[1]), "r"(a[2]), "r"(a[3]),
          "r"(b[0]), "r"(b[1]));
}

// ============================================================================
// Double-buffered fp16 NT GEMM mainloop, BK=32 (2 k16 steps / chunk).
// BM=BN=128, 256 threads (8 warps, 2m x 4n), warp tile 64x32.
// Prefetch converts f32->packed f16x2 at load time (16 prefetch regs).
// One __syncthreads per chunk; 32 mmas/warp between barriers.
// ============================================================================
__device__ __forceinline__ void gemm_main(const float* __restrict__ Asrc,
                                          const float* __restrict__ Bw,
                                          int bm, int bn,
                                          float (&acc)[4][4][4])
{
    __shared__ uint32_t sA[2][128 * SSTRW];
    __shared__ uint32_t sB[2][128 * SSTRW];

    const int tid  = threadIdx.x;
    const int wid  = tid >> 5;
    const int lane = tid & 31;
    const int lr4  = lane >> 2;
    const int lc4  = lane & 3;
    const int warp_m = (wid & 1) * 64;
    const int warp_n = (wid >> 1) * 32;

    // gmem mapping: 8 lanes cover one row's 32 floats (128B, coalesced);
    // each thread does rows qrow + q*32, q = 0..3, one float4 each.
    const int qrow = tid >> 3;           // 0..31
    const int qcol = (tid & 7) << 2;     // float col 0..28
    const int wcol = qcol >> 1;          // word col 0..14 (even)

    uint2 pA[4], pB[4];                  // packed-half prefetch (16 regs)

#define LOADPF(cc) do { int ko = (cc) * BKC + qcol; \
    _Pragma("unroll") \
    for (int q = 0; q < 4; q++) { \
        float4 a = *(const float4*)(Asrc + (bm + qrow + q * 32) * EMBED + ko); \
        float4 b = *(const float4*)(Bw   + (bn + qrow + q * 32) * EMBED + ko); \
        pA[q].x = h2(a.x, a.y); pA[q].y = h2(a.z, a.w); \
        pB[q].x = h2(b.x, b.y); pB[q].y = h2(b.z, b.w); \
    } } while (0)

#define STOREPF(buf) do { \
    _Pragma("unroll") \
    for (int q = 0; q < 4; q++) { \
        *(uint2*)&sA[buf][(qrow + q * 32) * SSTRW + wcol] = pA[q]; \
        *(uint2*)&sB[buf][(qrow + q * 32) * SSTRW + wcol] = pB[q]; \
    } } while (0)

    LOADPF(0);
    STOREPF(0);
    LOADPF(1);

    for (int c = 0; c < NCHUNK; c++) {
        __syncthreads();
        if (c + 1 < NCHUNK) {
            STOREPF((c + 1) & 1);
            if (c + 2 < NCHUNK) LOADPF(c + 2);
        }
        const uint32_t* cA = sA[c & 1];
        const uint32_t* cB = sB[c & 1];

#pragma unroll
        for (int ks = 0; ks < 2; ks++) {
            const int kb = ks * 8;
            uint32_t af[4][4], bf[4][2];
#pragma unroll
            for (int i = 0; i < 4; i++) {
                int m = warp_m + i * 16;
                af[i][0] = cA[(m + lr4    ) * SSTRW + kb + lc4    ];
                af[i][1] = cA[(m + lr4 + 8) * SSTRW + kb + lc4    ];
                af[i][2] = cA[(m + lr4    ) * SSTRW + kb + lc4 + 4];
                af[i][3] = cA[(m + lr4 + 8) * SSTRW + kb + lc4 + 4];
            }
#pragma unroll
            for (int j = 0; j < 4; j++) {
                int n = warp_n + j * 8;
                bf[j][0] = cB[(n + lr4) * SSTRW + kb + lc4    ];
                bf[j][1] = cB[(n + lr4) * SSTRW + kb + lc4 + 4];
            }
#pragma unroll
            for (int i = 0; i < 4; i++)
#pragma unroll
                for (int j = 0; j < 4; j++)
                    mma_f16(acc[i][j], af[i], bf[j]);
        }
    }
#undef LOADPF
#undef STOREPF
}

// ============================================================================
// Fused QKV projection
// ============================================================================
__global__ void __launch_bounds__(256, 2)
qkv_gemm(const float* __restrict__ x,
         const float* __restrict__ Wq, const float* __restrict__ Wk,
         const float* __restrict__ Wv,
         const float* __restrict__ bq, const float* __restrict__ bk,
         const float* __restrict__ bv)
{
    const int z = blockIdx.z;
    const float* Bw   = (z == 0) ? Wq : (z == 1) ? Wk : Wv;
    const float* bias = (z == 0) ? bq : (z == 1) ? bk : bv;
    float* C          = (z == 0) ? g_Q : (z == 1) ? g_K : g_V;

    const int bm = blockIdx.x * 128;
    const int bn = blockIdx.y * 128;

    float acc[4][4][4];
#pragma unroll
    for (int i = 0; i < 4; i++)
#pragma unroll
        for (int j = 0; j < 4; j++)
#pragma unroll
            for (int r = 0; r < 4; r++) acc[i][j][r] = 0.f;

    gemm_main(x, Bw, bm, bn, acc);

    const int tid  = threadIdx.x;
    const int wid  = tid >> 5;
    const int lane = tid & 31;
    const int lr4  = lane >> 2;
    const int lc4  = lane & 3;
    const int warp_m = (wid & 1) * 64;
    const int warp_n = (wid >> 1) * 32;

#pragma unroll
    for (int i = 0; i < 4; i++) {
#pragma unroll
        for (int j = 0; j < 4; j++) {
            int row0 = bm + warp_m + i * 16 + lr4;
            int col0 = bn + warp_n + j * 8 + 2 * lc4;
#pragma unroll
            for (int half = 0; half < 2; half++) {
                int row = row0 + half * 8;
                float2 o;
                o.x = acc[i][j][half * 2 + 0] + __ldg(bias + col0 + 0);
                o.y = acc[i][j][half * 2 + 1] + __ldg(bias + col0 + 1);
                int b   = row >> 11;
                int tok = row & 2047;
                int h   = col0 >> 6;
                int dh  = col0 & 63;
                *(float2*)&C[(((b << 4) + h) * SEQ + tok) * HDIM + dh] = o;
            }
        }
    }
}

// ============================================================================
// Output projection
// ============================================================================
__global__ void __launch_bounds__(256, 2)
out_gemm(const float* __restrict__ Wo, float* __restrict__ out)
{
    const int bm = blockIdx.x * 128;
    const int bn = blockIdx.y * 128;

    float acc[4][4][4];
#pragma unroll
    for (int i = 0; i < 4; i++)
#pragma unroll
        for (int j = 0; j < 4; j++)
#pragma unroll
            for (int r = 0; r < 4; r++) acc[i][j][r] = 0.f;

    gemm_main((const float*)g_C, Wo, bm, bn, acc);

    const int tid  = threadIdx.x;
    const int wid  = tid >> 5;
    const int lane = tid & 31;
    const int lr4  = lane >> 2;
    const int lc4  = lane & 3;
    const int warp_m = (wid & 1) * 64;
    const int warp_n = (wid >> 1) * 32;

#pragma unroll
    for (int i = 0; i < 4; i++) {
#pragma unroll
        for (int j = 0; j < 4; j++) {
            int row0 = bm + warp_m + i * 16 + lr4;
            int col0 = bn + warp_n + j * 8 + 2 * lc4;
#pragma unroll
            for (int half = 0; half < 2; half++) {
                int row = row0 + half * 8;
                float2 o;
                o.x = acc[i][j][half * 2 + 0];
                o.y = acc[i][j][half * 2 + 1];
                *(float2*)&out[row * EMBED + col0] = o;
            }
        }
    }
}

// ============================================================================
// Flash attention, fp16 mma. BQ=128, 8 warps x 16 q-rows, Q in registers.
// Double-buffered sK/sVt (1 sync per kv tile); K/V prefetched as packed
// halves (16 regs). Compute identical to round 8 (bit-identical results).
// ============================================================================
__global__ void __launch_bounds__(256, 2)
attn_mma()
{
    __shared__ uint32_t sK [2][64 * 32];
    __shared__ uint32_t sVt[2][64 * 32];

    const int tid  = threadIdx.x;
    const int wid  = tid >> 5;
    const int lane = tid & 31;
    const int lr4  = lane >> 2;
    const int lc4  = lane & 3;
    const int warp_m = wid * 16;
    const int q0 = blockIdx.x * 128;
    const int h  = blockIdx.y;
    const int b  = blockIdx.z;

    const float* Qb = g_Q + ((b * HEADS + h) * SEQ + q0) * HDIM;
    const float* Kb = g_K + ((b * HEADS + h) * SEQ) * HDIM;
    const float* Vb = g_V + ((b * HEADS + h) * SEQ) * HDIM;

    // K prefetch mapping (4 slices), V prefetch mapping (2 slices)
    const int krow = tid >> 4;            // base row (stride 16 over slices... see loop)
    const int kwc  = (tid & 15) << 1;     // word col 0..30 even
    (void)krow;

    // ---- Q fragments -> registers (scaled by Dh^-0.5 = 0.125) ----
    uint32_t qf[4][4];
    {
        const float* qr0 = Qb + (warp_m + lr4) * HDIM;
        const float* qr1 = qr0 + 8 * HDIM;
#pragma unroll
        for (int ks = 0; ks < 4; ks++) {
            int c = ks * 16 + 2 * lc4;
            qf[ks][0] = h2(qr0[c    ] * 0.125f, qr0[c + 1] * 0.125f);
            qf[ks][1] = h2(qr1[c    ] * 0.125f, qr1[c + 1] * 0.125f);
            qf[ks][2] = h2(qr0[c + 8] * 0.125f, qr0[c + 9] * 0.125f);
            qf[ks][3] = h2(qr1[c + 8] * 0.125f, qr1[c + 9] * 0.125f);
        }
    }

    uint2    pk[4];        // packed K prefetch (8 regs)
    uint32_t pv[2][4];     // packed Vt prefetch (8 regs)

#define LOADKV(tt) do { const int kv0 = (tt) * 64; \
    _Pragma("unroll") \
    for (int r = 0; r < 4; r++) { \
        int idx = tid + r * 256; \
        int row = idx >> 4; \
        float4 kv = *(const float4*)&Kb[(kv0 + row) * HDIM + (kwc << 1)]; \
        pk[r].x = h2(kv.x, kv.y); pk[r].y = h2(kv.z, kv.w); \
    } \
    _Pragma("unroll") \
    for (int r = 0; r < 2; r++) { \
        int t2  = tid + r * 256; \
        int kv2 = t2 >> 4; \
        int d4  = (t2 & 15) << 2; \
        float4 v0 = *(const float4*)&Vb[(kv0 + 2 * kv2    ) * HDIM + d4]; \
        float4 v1 = *(const float4*)&Vb[(kv0 + 2 * kv2 + 1) * HDIM + d4]; \
        pv[r][0] = h2(v0.x, v1.x); pv[r][1] = h2(v0.y, v1.y); \
        pv[r][2] = h2(v0.z, v1.z); pv[r][3] = h2(v0.w, v1.w); \
    } } while (0)

#define STOREKV(buf) do { \
    _Pragma("unroll") \
    for (int r = 0; r < 4; r++) { \
        int idx = tid + r * 256; \
        int row = idx >> 4; \
        *(uint2*)&sK[buf][row * 32 + (kwc ^ ((row & 7) << 2))] = pk[r]; \
    } \
    _Pragma("unroll") \
    for (int r = 0; r < 2; r++) { \
        int t2  = tid + r * 256; \
        int kv2 = t2 >> 4; \
        int d4  = (t2 & 15) << 2; \
        sVt[buf][(d4 + 0) * 32 + (kv2 ^ (((d4 + 0) & 7) << 2))] = pv[r][0]; \
        sVt[buf][(d4 + 1) * 32 + (kv2 ^ (((d4 + 1) & 7) << 2))] = pv[r][1]; \
        sVt[buf][(d4 + 2) * 32 + (kv2 ^ (((d4 + 2) & 7) << 2))] = pv[r][2]; \
        sVt[buf][(d4 + 3) * 32 + (kv2 ^ (((d4 + 3) & 7) << 2))] = pv[r][3]; \
    } } while (0)

    float out[8][4];
#pragma unroll
    for (int n = 0; n < 8; n++)
#pragma unroll
        for (int c = 0; c < 4; c++) out[n][c] = 0.f;
    float m0 = -INFINITY, m1 = -INFINITY, l0 = 0.f, l1 = 0.f;

    const int NT = SEQ / 64;   // 32
    LOADKV(0);
    STOREKV(0);
    LOADKV(1);

    for (int t = 0; t < NT; t++) {
        __syncthreads();                 // buf[t&1] visible; buf[(t+1)&1] readers done
        if (t + 1 < NT) {
            STOREKV((t + 1) & 1);
            if (t + 2 < NT) LOADKV(t + 2);
        }
        const uint32_t* cK = sK [t & 1];
        const uint32_t* cV = sVt[t & 1];

        // ---- QK^T: 4 k16 steps x 8 kv-tiles ----
        float s[8][4];
#pragma unroll
        for (int j = 0; j < 8; j++)
#pragma unroll
            for (int c = 0; c < 4; c++) s[j][c] = 0.f;

#pragma unroll
        for (int ks = 0; ks < 4; ks++) {
            const int kb = ks * 8;
#pragma unroll
            for (int j = 0; j < 8; j++) {
                uint32_t bf[2];
                const int rb = j * 8 + lr4;
                bf[0] = cK[rb * 32 + ((kb + lc4    ) ^ (lr4 << 2))];
                bf[1] = cK[rb * 32 + ((kb + lc4 + 4) ^ (lr4 << 2))];
                mma_f16(s[j], qf[ks], bf);
            }
        }

        // ---- online softmax ----
        float mx0 = -INFINITY, mx1 = -INFINITY;
#pragma unroll
        for (int j = 0; j < 8; j++) {
            mx0 = fmaxf(mx0, fmaxf(s[j][0], s[j][1]));
            mx1 = fmaxf(mx1, fmaxf(s[j][2], s[j][3]));
        }
        mx0 = fmaxf(mx0, __shfl_xor_sync(0xffffffffu, mx0, 1));
        mx0 = fmaxf(mx0, __shfl_xor_sync(0xffffffffu, mx0, 2));
        mx1 = fmaxf(mx1, __shfl_xor_sync(0xffffffffu, mx1, 1));
        mx1 = fmaxf(mx1, __shfl_xor_sync(0xffffffffu, mx1, 2));
        float mn0 = fmaxf(m0, mx0), mn1 = fmaxf(m1, mx1);
        float rs0 = __expf(m0 - mn0), rs1 = __expf(m1 - mn1);
        m0 = mn0; m1 = mn1;
        float sum0 = 0.f, sum1 = 0.f;
#pragma unroll
        for (int j = 0; j < 8; j++) {
            s[j][0] = __expf(s[j][0] - mn0);
            s[j][1] = __expf(s[j][1] - mn0);
            sum0 += s[j][0] + s[j][1];
            s[j][2] = __expf(s[j][2] - mn1);
            s[j][3] = __expf(s[j][3] - mn1);
            sum1 += s[j][2] + s[j][3];
        }
        sum0 += __shfl_xor_sync(0xffffffffu, sum0, 1);
        sum0 += __shfl_xor_sync(0xffffffffu, sum0, 2);
        sum1 += __shfl_xor_sync(0xffffffffu, sum1, 1);
        sum1 += __shfl_xor_sync(0xffffffffu, sum1, 2);
        l0 = l0 * rs0 + sum0;
        l1 = l1 * rs1 + sum1;
#pragma unroll
        for (int n = 0; n < 8; n++) {
            out[n][0] *= rs0; out[n][1] *= rs0;
            out[n][2] *= rs1; out[n][3] *= rs1;
        }

        // ---- PV: 4 k16 steps x 8 d-tiles, P direct from registers ----
#pragma unroll
        for (int jp = 0; jp < 4; jp++) {
            uint32_t a[4];
            a[0] = h2(s[2 * jp    ][0], s[2 * jp    ][1]);
            a[1] = h2(s[2 * jp    ][2], s[2 * jp    ][3]);
            a[2] = h2(s[2 * jp + 1][0], s[2 * jp + 1][1]);
            a[3] = h2(s[2 * jp + 1][2], s[2 * jp + 1][3]);
            const int kb = jp * 8;
#pragma unroll
            for (int n = 0; n < 8; n++) {
                uint32_t bf[2];
                const int rb = n * 8 + lr4;
                bf[0] = cV[rb * 32 + ((kb + lc4    ) ^ (lr4 << 2))];
                bf[1] = cV[rb * 32 + ((kb + lc4 + 4) ^ (lr4 << 2))];
                mma_f16(out[n], a, bf);
            }
        }
    }
#undef LOADKV
#undef STOREKV

    // ---- epilogue: ctx[b][q][h*64 + dh] ----
    const float inv0 = 1.f / l0, inv1 = 1.f / l1;
    float* Cb = g_C + (b * SEQ + q0) * EMBED + h * HDIM;
    const int r0 = warp_m + lr4, r1 = r0 + 8;
#pragma unroll
    for (int n = 0; n < 8; n++) {
        int col = n * 8 + 2 * lc4;
        float2 o;
        o.x = out[n][0] * inv0; o.y = out[n][1] * inv0;
        *(float2*)&Cb[r0 * EMBED + col] = o;
        o.x = out[n][2] * inv1; o.y = out[n][3] * inv1;
        *(float2*)&Cb[r1 * EMBED + col] = o;
    }
}

// ============================================================================
extern "C" void kernel_launch(void* const* d_in, const int* in_sizes, int n_in,
                              void* d_out, int out_size)
{
    (void)in_sizes; (void)n_in; (void)out_size;
    const float* x  = (const float*)d_in[0];
    const float* Wq = (const float*)d_in[1];
    const float* bq = (const float*)d_in[2];
    const float* Wk = (const float*)d_in[3];
    const float* bk = (const float*)d_in[4];
    const float* Wv = (const float*)d_in[5];
    const float* bv = (const float*)d_in[6];
    const float* Wo = (const float*)d_in[7];
    float* out = (float*)d_out;

    qkv_gemm<<<dim3(MTOT / 128, EMBED / 128, 3), 256>>>(x, Wq, Wk, Wv, bq, bk, bv);

    attn_mma<<<dim3(SEQ / 128, HEADS, BATCH), 256>>>();

    out_gemm<<<dim3(MTOT / 128, EMBED / 128), 256>>>(Wo, out);
}

// round 10
// speedup vs baseline: 1.8212x; 1.0639x over previous
#include <cuda_runtime.h>
#include <cuda_fp16.h>
#include <math.h>
#include <stdint.h>

#define EMBED 1024
#define HEADS 16
#define HDIM  64
#define BATCH 4
#define SEQ   2048
#define MTOT  (BATCH * SEQ)   /* 8192 */

#define BKC     32            /* GEMM K floats per chunk (2 x k16 mma) */
#define NCHUNK  (EMBED / BKC) /* 32 */
#define SSTRW   20            /* GEMM smem row stride in 32-bit words */

// ---- scratch (device globals; no allocations allowed) ----
__device__ float g_Q[BATCH * HEADS * SEQ * HDIM];  // [B][H][N][Dh]
__device__ float g_K[BATCH * HEADS * SEQ * HDIM];
__device__ float g_V[BATCH * HEADS * SEQ * HDIM];
__device__ float g_C[MTOT * EMBED];                // attention ctx, [B][N][D]

// pack two floats -> f16x2 (round-to-nearest; .x = lo)
__device__ __forceinline__ uint32_t h2(float lo, float hi) {
    __half2 h = __floats2half2_rn(lo, hi);
    return *(uint32_t*)&h;
}

// D += A(16x16) * B(16x8), f16 inputs, f32 accum
__device__ __forceinline__ void mma_f16(float* d, const uint32_t* a, const uint32_t* b) {
    asm volatile(
        "mma.sync.aligned.m16n8k16.row.col.f32.f16.f16.f32 "
        "{%0,%1,%2,%3}, {%4,%5,%6,%7}, {%8,%9}, {%0,%1,%2,%3};"
        : "+f"(d[0]), "+f"(d[1]), "+f"(d[2]), "+f"(d[3])
        : "r"(a[0]), "r"(a[1]), "r"(a[2]), "r"(a[3]),
          "r"(b[0]), "r"(b[1]));
}

// 4x m8n8 b16 matrices in one shot; lane l supplies the row address for
// matrix l>>3, row l&7. Output distribution matches mma fragment layout.
__device__ __forceinline__ void ldsm_x4(uint32_t& r0, uint32_t& r1,
                                        uint32_t& r2, uint32_t& r3,
                                        uint32_t addr) {
    asm volatile("ldmatrix.sync.aligned.m8n8.x4.shared.b16 {%0,%1,%2,%3}, [%4];"
                 : "=r"(r0), "=r"(r1), "=r"(r2), "=r"(r3) : "r"(addr));
}

// ============================================================================
// Double-buffered fp16 NT GEMM mainloop, BK=32, fragments via ldmatrix.
// BM=BN=128, 256 threads (8 warps, 2m x 4n), warp tile 64x32.
// ============================================================================
__device__ __forceinline__ void gemm_main(const float* __restrict__ Asrc,
                                          const float* __restrict__ Bw,
                                          int bm, int bn,
                                          float (&acc)[4][4][4])
{
    __shared__ uint32_t sA[2][128 * SSTRW];
    __shared__ uint32_t sB[2][128 * SSTRW];

    const int tid  = threadIdx.x;
    const int wid  = tid >> 5;
    const int lane = tid & 31;
    const int warp_m = (wid & 1) * 64;
    const int warp_n = (wid >> 1) * 32;

    // gmem mapping: 8 lanes cover one row's 32 floats (128B, coalesced)
    const int qrow = tid >> 3;
    const int qcol = (tid & 7) << 2;
    const int wcol = qcol >> 1;

    // ldmatrix per-lane offsets (bytes)
    // A: mat = lane>>3: mat0 rows m..m+7 @kb, mat1 rows m+8.. @kb,
    //    mat2 rows m..m+7 @kb+4, mat3 rows m+8.. @kb+4  (a0,a1,a2,a3 order)
    const int arow = ((lane >> 3) & 1) * 8 + (lane & 7);
    const int acol = (lane >> 4) << 2;
    const uint32_t aoff = ((warp_m + arow) * SSTRW + acol) * 4;
    // B: mat0 rows n..n+7 @kb (b0 of j), mat1 rows n..n+7 @kb+4 (b1 of j),
    //    mat2 rows n+8.. @kb (b0 of j+1), mat3 rows n+8.. @kb+4 (b1 of j+1)
    const int brow = ((lane >> 4) & 1) * 8 + (lane & 7);
    const int bcol = ((lane >> 3) & 1) << 2;
    const uint32_t boff = ((warp_n + brow) * SSTRW + bcol) * 4;

    const uint32_t sAb[2] = { (uint32_t)__cvta_generic_to_shared(&sA[0][0]),
                              (uint32_t)__cvta_generic_to_shared(&sA[1][0]) };
    const uint32_t sBb[2] = { (uint32_t)__cvta_generic_to_shared(&sB[0][0]),
                              (uint32_t)__cvta_generic_to_shared(&sB[1][0]) };

    uint2 pA[4], pB[4];

#define LOADPF(cc) do { int ko = (cc) * BKC + qcol; \
    _Pragma("unroll") \
    for (int q = 0; q < 4; q++) { \
        float4 a = *(const float4*)(Asrc + (bm + qrow + q * 32) * EMBED + ko); \
        float4 b = *(const float4*)(Bw   + (bn + qrow + q * 32) * EMBED + ko); \
        pA[q].x = h2(a.x, a.y); pA[q].y = h2(a.z, a.w); \
        pB[q].x = h2(b.x, b.y); pB[q].y = h2(b.z, b.w); \
    } } while (0)

#define STOREPF(buf) do { \
    _Pragma("unroll") \
    for (int q = 0; q < 4; q++) { \
        *(uint2*)&sA[buf][(qrow + q * 32) * SSTRW + wcol] = pA[q]; \
        *(uint2*)&sB[buf][(qrow + q * 32) * SSTRW + wcol] = pB[q]; \
    } } while (0)

    LOADPF(0);
    STOREPF(0);
    LOADPF(1);

    for (int c = 0; c < NCHUNK; c++) {
        __syncthreads();
        if (c + 1 < NCHUNK) {
            STOREPF((c + 1) & 1);
            if (c + 2 < NCHUNK) LOADPF(c + 2);
        }
        const uint32_t cAa = sAb[c & 1] + aoff;
        const uint32_t cBa = sBb[c & 1] + boff;

#pragma unroll
        for (int ks = 0; ks < 2; ks++) {
            const uint32_t kbb = ks * 8 * 4;   // byte offset of k-step
            uint32_t af[4][4], bf[4][2];
#pragma unroll
            for (int i = 0; i < 4; i++)
                ldsm_x4(af[i][0], af[i][1], af[i][2], af[i][3],
                        cAa + i * 16 * SSTRW * 4 + kbb);
#pragma unroll
            for (int jp = 0; jp < 2; jp++)
                ldsm_x4(bf[2 * jp][0], bf[2 * jp][1],
                        bf[2 * jp + 1][0], bf[2 * jp + 1][1],
                        cBa + jp * 16 * SSTRW * 4 + kbb);
#pragma unroll
            for (int i = 0; i < 4; i++)
#pragma unroll
                for (int j = 0; j < 4; j++)
                    mma_f16(acc[i][j], af[i], bf[j]);
        }
    }
#undef LOADPF
#undef STOREPF
}

// ============================================================================
// Fused QKV projection
// ============================================================================
__global__ void __launch_bounds__(256, 2)
qkv_gemm(const float* __restrict__ x,
         const float* __restrict__ Wq, const float* __restrict__ Wk,
         const float* __restrict__ Wv,
         const float* __restrict__ bq, const float* __restrict__ bk,
         const float* __restrict__ bv)
{
    const int z = blockIdx.z;
    const float* Bw   = (z == 0) ? Wq : (z == 1) ? Wk : Wv;
    const float* bias = (z == 0) ? bq : (z == 1) ? bk : bv;
    float* C          = (z == 0) ? g_Q : (z == 1) ? g_K : g_V;

    const int bm = blockIdx.x * 128;
    const int bn = blockIdx.y * 128;

    float acc[4][4][4];
#pragma unroll
    for (int i = 0; i < 4; i++)
#pragma unroll
        for (int j = 0; j < 4; j++)
#pragma unroll
            for (int r = 0; r < 4; r++) acc[i][j][r] = 0.f;

    gemm_main(x, Bw, bm, bn, acc);

    const int tid  = threadIdx.x;
    const int wid  = tid >> 5;
    const int lane = tid & 31;
    const int lr4  = lane >> 2;
    const int lc4  = lane & 3;
    const int warp_m = (wid & 1) * 64;
    const int warp_n = (wid >> 1) * 32;

#pragma unroll
    for (int i = 0; i < 4; i++) {
#pragma unroll
        for (int j = 0; j < 4; j++) {
            int row0 = bm + warp_m + i * 16 + lr4;
            int col0 = bn + warp_n + j * 8 + 2 * lc4;
#pragma unroll
            for (int half = 0; half < 2; half++) {
                int row = row0 + half * 8;
                float2 o;
                o.x = acc[i][j][half * 2 + 0] + __ldg(bias + col0 + 0);
                o.y = acc[i][j][half * 2 + 1] + __ldg(bias + col0 + 1);
                int b   = row >> 11;
                int tok = row & 2047;
                int h   = col0 >> 6;
                int dh  = col0 & 63;
                *(float2*)&C[(((b << 4) + h) * SEQ + tok) * HDIM + dh] = o;
            }
        }
    }
}

// ============================================================================
// Output projection
// ============================================================================
__global__ void __launch_bounds__(256, 2)
out_gemm(const float* __restrict__ Wo, float* __restrict__ out)
{
    const int bm = blockIdx.x * 128;
    const int bn = blockIdx.y * 128;

    float acc[4][4][4];
#pragma unroll
    for (int i = 0; i < 4; i++)
#pragma unroll
        for (int j = 0; j < 4; j++)
#pragma unroll
            for (int r = 0; r < 4; r++) acc[i][j][r] = 0.f;

    gemm_main((const float*)g_C, Wo, bm, bn, acc);

    const int tid  = threadIdx.x;
    const int wid  = tid >> 5;
    const int lane = tid & 31;
    const int lr4  = lane >> 2;
    const int lc4  = lane & 3;
    const int warp_m = (wid & 1) * 64;
    const int warp_n = (wid >> 1) * 32;

#pragma unroll
    for (int i = 0; i < 4; i++) {
#pragma unroll
        for (int j = 0; j < 4; j++) {
            int row0 = bm + warp_m + i * 16 + lr4;
            int col0 = bn + warp_n + j * 8 + 2 * lc4;
#pragma unroll
            for (int half = 0; half < 2; half++) {
                int row = row0 + half * 8;
                float2 o;
                o.x = acc[i][j][half * 2 + 0];
                o.y = acc[i][j][half * 2 + 1];
                *(float2*)&out[row * EMBED + col0] = o;
            }
        }
    }
}

// ============================================================================
// Flash attention, fp16 mma + ldmatrix. BQ=128, 8 warps x 16 q-rows,
// Q in registers, double-buffered sK/sVt, 1 sync/tile.
// K/V fragments via ldmatrix.x4 with swizzle folded into per-lane address.
// ============================================================================
__global__ void __launch_bounds__(256, 2)
attn_mma()
{
    __shared__ uint32_t sK [2][64 * 32];
    __shared__ uint32_t sVt[2][64 * 32];

    const int tid  = threadIdx.x;
    const int wid  = tid >> 5;
    const int lane = tid & 31;
    const int lr4  = lane >> 2;
    const int lc4  = lane & 3;
    const int warp_m = wid * 16;
    const int q0 = blockIdx.x * 128;
    const int h  = blockIdx.y;
    const int b  = blockIdx.z;

    const float* Qb = g_Q + ((b * HEADS + h) * SEQ + q0) * HDIM;
    const float* Kb = g_K + ((b * HEADS + h) * SEQ) * HDIM;
    const float* Vb = g_V + ((b * HEADS + h) * SEQ) * HDIM;

    const int kwc = (tid & 15) << 1;

    // ldmatrix per-lane pieces: mat = lane>>3
    //   mat0: rows t..t+7 @kb   (b0 of tile t)    mat1: rows t..t+7 @kb+4
    //   mat2: rows t+8..  @kb   (b0 of tile t+1)  mat3: rows t+8..  @kb+4
    const int lrow = ((lane >> 4) & 1) * 8 + (lane & 7);
    const int lcol = ((lane >> 3) & 1) << 2;
    const int xorv = (lane & 7) << 2;

    const uint32_t sKb[2] = { (uint32_t)__cvta_generic_to_shared(&sK[0][0]),
                              (uint32_t)__cvta_generic_to_shared(&sK[1][0]) };
    const uint32_t sVb[2] = { (uint32_t)__cvta_generic_to_shared(&sVt[0][0]),
                              (uint32_t)__cvta_generic_to_shared(&sVt[1][0]) };

    // ---- Q fragments -> registers (scaled by Dh^-0.5 = 0.125) ----
    uint32_t qf[4][4];
    {
        const float* qr0 = Qb + (warp_m + lr4) * HDIM;
        const float* qr1 = qr0 + 8 * HDIM;
#pragma unroll
        for (int ks = 0; ks < 4; ks++) {
            int c = ks * 16 + 2 * lc4;
            qf[ks][0] = h2(qr0[c    ] * 0.125f, qr0[c + 1] * 0.125f);
            qf[ks][1] = h2(qr1[c    ] * 0.125f, qr1[c + 1] * 0.125f);
            qf[ks][2] = h2(qr0[c + 8] * 0.125f, qr0[c + 9] * 0.125f);
            qf[ks][3] = h2(qr1[c + 8] * 0.125f, qr1[c + 9] * 0.125f);
        }
    }

    uint2    pk[4];
    uint32_t pv[2][4];

#define LOADKV(tt) do { const int kv0 = (tt) * 64; \
    _Pragma("unroll") \
    for (int r = 0; r < 4; r++) { \
        int idx = tid + r * 256; \
        int row = idx >> 4; \
        float4 kv = *(const float4*)&Kb[(kv0 + row) * HDIM + (kwc << 1)]; \
        pk[r].x = h2(kv.x, kv.y); pk[r].y = h2(kv.z, kv.w); \
    } \
    _Pragma("unroll") \
    for (int r = 0; r < 2; r++) { \
        int t2  = tid + r * 256; \
        int kv2 = t2 >> 4; \
        int d4  = (t2 & 15) << 2; \
        float4 v0 = *(const float4*)&Vb[(kv0 + 2 * kv2    ) * HDIM + d4]; \
        float4 v1 = *(const float4*)&Vb[(kv0 + 2 * kv2 + 1) * HDIM + d4]; \
        pv[r][0] = h2(v0.x, v1.x); pv[r][1] = h2(v0.y, v1.y); \
        pv[r][2] = h2(v0.z, v1.z); pv[r][3] = h2(v0.w, v1.w); \
    } } while (0)

#define STOREKV(buf) do { \
    _Pragma("unroll") \
    for (int r = 0; r < 4; r++) { \
        int idx = tid + r * 256; \
        int row = idx >> 4; \
        *(uint2*)&sK[buf][row * 32 + (kwc ^ ((row & 7) << 2))] = pk[r]; \
    } \
    _Pragma("unroll") \
    for (int r = 0; r < 2; r++) { \
        int t2  = tid + r * 256; \
        int kv2 = t2 >> 4; \
        int d4  = (t2 & 15) << 2; \
        sVt[buf][(d4 + 0) * 32 + (kv2 ^ (((d4 + 0) & 7) << 2))] = pv[r][0]; \
        sVt[buf][(d4 + 1) * 32 + (kv2 ^ (((d4 + 1) & 7) << 2))] = pv[r][1]; \
        sVt[buf][(d4 + 2) * 32 + (kv2 ^ (((d4 + 2) & 7) << 2))] = pv[r][2]; \
        sVt[buf][(d4 + 3) * 32 + (kv2 ^ (((d4 + 3) & 7) << 2))] = pv[r][3]; \
    } } while (0)

    float out[8][4];
#pragma unroll
    for (int n = 0; n < 8; n++)
#pragma unroll
        for (int c = 0; c < 4; c++) out[n][c] = 0.f;
    float m0 = -INFINITY, m1 = -INFINITY, l0 = 0.f, l1 = 0.f;

    const int NT = SEQ / 64;   // 32
    LOADKV(0);
    STOREKV(0);
    LOADKV(1);

    for (int t = 0; t < NT; t++) {
        __syncthreads();
        if (t + 1 < NT) {
            STOREKV((t + 1) & 1);
            if (t + 2 < NT) LOADKV(t + 2);
        }
        const uint32_t cKa = sKb[t & 1];
        const uint32_t cVa = sVb[t & 1];

        // ---- QK^T: 4 k16 steps x 4 kv tile-pairs (ldmatrix.x4) ----
        float s[8][4];
#pragma unroll
        for (int j = 0; j < 8; j++)
#pragma unroll
            for (int c = 0; c < 4; c++) s[j][c] = 0.f;

#pragma unroll
        for (int ks = 0; ks < 4; ks++) {
            const int colk = (ks * 8 + lcol) ^ xorv;
#pragma unroll
            for (int jp = 0; jp < 4; jp++) {
                uint32_t bf[4];
                ldsm_x4(bf[0], bf[1], bf[2], bf[3],
                        cKa + ((jp * 16 + lrow) * 32 + colk) * 4);
                mma_f16(s[2 * jp    ], qf[ks], bf);
                mma_f16(s[2 * jp + 1], qf[ks], bf + 2);
            }
        }

        // ---- online softmax ----
        float mx0 = -INFINITY, mx1 = -INFINITY;
#pragma unroll
        for (int j = 0; j < 8; j++) {
            mx0 = fmaxf(mx0, fmaxf(s[j][0], s[j][1]));
            mx1 = fmaxf(mx1, fmaxf(s[j][2], s[j][3]));
        }
        mx0 = fmaxf(mx0, __shfl_xor_sync(0xffffffffu, mx0, 1));
        mx0 = fmaxf(mx0, __shfl_xor_sync(0xffffffffu, mx0, 2));
        mx1 = fmaxf(mx1, __shfl_xor_sync(0xffffffffu, mx1, 1));
        mx1 = fmaxf(mx1, __shfl_xor_sync(0xffffffffu, mx1, 2));
        float mn0 = fmaxf(m0, mx0), mn1 = fmaxf(m1, mx1);
        float rs0 = __expf(m0 - mn0), rs1 = __expf(m1 - mn1);
        m0 = mn0; m1 = mn1;
        float sum0 = 0.f, sum1 = 0.f;
#pragma unroll
        for (int j = 0; j < 8; j++) {
            s[j][0] = __expf(s[j][0] - mn0);
            s[j][1] = __expf(s[j][1] - mn0);
            sum0 += s[j][0] + s[j][1];
            s[j][2] = __expf(s[j][2] - mn1);
            s[j][3] = __expf(s[j][3] - mn1);
            sum1 += s[j][2] + s[j][3];
        }
        sum0 += __shfl_xor_sync(0xffffffffu, sum0, 1);
        sum0 += __shfl_xor_sync(0xffffffffu, sum0, 2);
        sum1 += __shfl_xor_sync(0xffffffffu, sum1, 1);
        sum1 += __shfl_xor_sync(0xffffffffu, sum1, 2);
        l0 = l0 * rs0 + sum0;
        l1 = l1 * rs1 + sum1;
#pragma unroll
        for (int n = 0; n < 8; n++) {
            out[n][0] *= rs0; out[n][1] *= rs0;
            out[n][2] *= rs1; out[n][3] *= rs1;
        }

        // ---- PV: 4 k16 steps x 4 d tile-pairs (ldmatrix.x4) ----
#pragma unroll
        for (int jp = 0; jp < 4; jp++) {
            uint32_t a[4];
            a[0] = h2(s[2 * jp    ][0], s[2 * jp    ][1]);
            a[1] = h2(s[2 * jp    ][2], s[2 * jp    ][3]);
            a[2] = h2(s[2 * jp + 1][0], s[2 * jp + 1][1]);
            a[3] = h2(s[2 * jp + 1][2], s[2 * jp + 1][3]);
            const int colv = (jp * 8 + lcol) ^ xorv;
#pragma unroll
            for (int np = 0; np < 4; np++) {
                uint32_t bf[4];
                ldsm_x4(bf[0], bf[1], bf[2], bf[3],
                        cVa + ((np * 16 + lrow) * 32 + colv) * 4);
                mma_f16(out[2 * np    ], a, bf);
                mma_f16(out[2 * np + 1], a, bf + 2);
            }
        }
    }
#undef LOADKV
#undef STOREKV

    // ---- epilogue: ctx[b][q][h*64 + dh] ----
    const float inv0 = 1.f / l0, inv1 = 1.f / l1;
    float* Cb = g_C + (b * SEQ + q0) * EMBED + h * HDIM;
    const int r0 = warp_m + lr4, r1 = r0 + 8;
#pragma unroll
    for (int n = 0; n < 8; n++) {
        int col = n * 8 + 2 * lc4;
        float2 o;
        o.x = out[n][0] * inv0; o.y = out[n][1] * inv0;
        *(float2*)&Cb[r0 * EMBED + col] = o;
        o.x = out[n][2] * inv1; o.y = out[n][3] * inv1;
        *(float2*)&Cb[r1 * EMBED + col] = o;
    }
}

// ============================================================================
extern "C" void kernel_launch(void* const* d_in, const int* in_sizes, int n_in,
                              void* d_out, int out_size)
{
    (void)in_sizes; (void)n_in; (void)out_size;
    const float* x  = (const float*)d_in[0];
    const float* Wq = (const float*)d_in[1];
    const float* bq = (const float*)d_in[2];
    const float* Wk = (const float*)d_in[3];
    const float* bk = (const float*)d_in[4];
    const float* Wv = (const float*)d_in[5];
    const float* bv = (const float*)d_in[6];
    const float* Wo = (const float*)d_in[7];
    float* out = (float*)d_out;

    qkv_gemm<<<dim3(MTOT / 128, EMBED / 128, 3), 256>>>(x, Wq, Wk, Wv, bq, bk, bv);

    attn_mma<<<dim3(SEQ / 128, HEADS, BATCH), 256>>>();

    out_gemm<<<dim3(MTOT / 128, EMBED / 128), 256>>>(Wo, out);
}